// round 3
// baseline (speedup 1.0000x reference)
#include <cuda_runtime.h>
#include <cuda_bf16.h>
#include <cstdint>

// LSTM: B=2048, T=512, F=64, H=16 (4H=64 gate cols), MLP 16->8->4->1.
// One warp per batch. Lane l owns gate columns l and l+32.
// Weights held as packed f32-pairs in registers; dots via fma.rn.f32x2.
// R2: LDS.128 chunked x/h reads + depth-4 software pipeline + 4 acc chains.

#define ULL unsigned long long

static constexpr int Bsz = 2048;
static constexpr int T   = 512;
static constexpr int G   = 64;   // 4*H

__device__ __forceinline__ ULL f2pack(float lo, float hi) {
    ULL r; asm("mov.b64 %0, {%1, %2};" : "=l"(r) : "f"(lo), "f"(hi)); return r;
}
__device__ __forceinline__ void f2unpack(ULL v, float& lo, float& hi) {
    asm("mov.b64 {%0, %1}, %2;" : "=f"(lo), "=f"(hi) : "l"(v));
}
__device__ __forceinline__ ULL ffma2(ULL a, ULL b, ULL c) {
    ULL d; asm("fma.rn.f32x2 %0, %1, %2, %3;" : "=l"(d) : "l"(a), "l"(b), "l"(c)); return d;
}
__device__ __forceinline__ ULL fadd2(ULL a, ULL b) {
    ULL d; asm("add.rn.f32x2 %0, %1, %2;" : "=l"(d) : "l"(a), "l"(b)); return d;
}
__device__ __forceinline__ float fast_sigmoid(float x) {
    return __fdividef(1.0f, 1.0f + __expf(-x));
}

__global__ void __launch_bounds__(128)
lstm_fused_kernel(const float* __restrict__ x,
                  const float* __restrict__ Wx,   // [64, 64]
                  const float* __restrict__ Wh,   // [16, 64]
                  const float* __restrict__ bias, // [64]
                  const float* __restrict__ W2,   // [16, 8]
                  const float* __restrict__ b2,   // [8]
                  const float* __restrict__ W3,   // [8, 4]
                  const float* __restrict__ b3,   // [4]
                  const float* __restrict__ Wo,   // [4, 1]
                  const float* __restrict__ bo,   // [1]
                  float* __restrict__ out)        // [B]
{
    const int lane  = threadIdx.x & 31;
    const int w     = threadIdx.x >> 5;
    const int batch = blockIdx.x * 4 + w;

    // 16B-aligned staging so the reader side can use LDS.128.
    __shared__ ulonglong2 sx4[4][16];  // x_t: 16 chunks x 2 packed pairs (64 floats)
    __shared__ ulonglong2 sh4[4][4];   // h:    4 chunks x 2 packed pairs (16 floats)

    // ---- register-resident weight pairs over k ----
    ULL wxa[32], wxb[32], wha[8], whb[8];
#pragma unroll
    for (int kk = 0; kk < 32; kk++) {
        wxa[kk] = f2pack(__ldg(&Wx[(2 * kk) * G + lane]),
                         __ldg(&Wx[(2 * kk + 1) * G + lane]));
        wxb[kk] = f2pack(__ldg(&Wx[(2 * kk) * G + lane + 32]),
                         __ldg(&Wx[(2 * kk + 1) * G + lane + 32]));
    }
#pragma unroll
    for (int kk = 0; kk < 8; kk++) {
        wha[kk] = f2pack(__ldg(&Wh[(2 * kk) * G + lane]),
                         __ldg(&Wh[(2 * kk + 1) * G + lane]));
        whb[kk] = f2pack(__ldg(&Wh[(2 * kk) * G + lane + 32]),
                         __ldg(&Wh[(2 * kk + 1) * G + lane + 32]));
    }
    const float bA = __ldg(&bias[lane]);
    const float bB = __ldg(&bias[lane + 32]);

    if (lane < 16) ((float*)sh4[w])[lane] = 0.0f;
    float c_state = 0.0f;

    const float2* xrow = reinterpret_cast<const float2*>(x + (size_t)batch * T * 64) + lane;
    float2 xc = __ldg(xrow);          // t = 0
    float2 xn = __ldg(xrow + 32);     // t = 1

    for (int t = 0; t < T; t++) {
        // stage x_t (pair index = lane)
        reinterpret_cast<float2*>(sx4[w])[lane] = xc;
        __syncwarp();

        // distance-2 global prefetch of the x stream
        int tp = (t + 2 < T) ? (t + 2) : (T - 1);
        float2 xf = __ldg(xrow + tp * 32);

        // h pairs: load all 8 now (LDS.128 x4); consumed ~120 cyc later.
        ULL hp[8];
        {
            ulonglong2 v0 = sh4[w][0], v1 = sh4[w][1], v2 = sh4[w][2], v3 = sh4[w][3];
            hp[0] = v0.x; hp[1] = v0.y; hp[2] = v1.x; hp[3] = v1.y;
            hp[4] = v2.x; hp[5] = v2.y; hp[6] = v3.x; hp[7] = v3.y;
        }

        // x chunk ring: depth 4 (prefetch distance = 4 chunks = 16 FMA2 issues)
        ULL xp[8];
        {
            ulonglong2 v0 = sx4[w][0], v1 = sx4[w][1], v2 = sx4[w][2], v3 = sx4[w][3];
            xp[0] = v0.x; xp[1] = v0.y; xp[2] = v1.x; xp[3] = v1.y;
            xp[4] = v2.x; xp[5] = v2.y; xp[6] = v3.x; xp[7] = v3.y;
        }

        // 4 independent accumulator chains; biases folded into init.
        ULL aa0 = f2pack(bA, 0.0f), aa1 = 0ULL;
        ULL ab0 = f2pack(bB, 0.0f), ab1 = 0ULL;

#pragma unroll
        for (int j = 0; j < 16; j++) {
            const int s = j & 3;
            ULL p0 = xp[2 * s], p1 = xp[2 * s + 1];
            aa0 = ffma2(p0, wxa[2 * j],     aa0);
            ab0 = ffma2(p0, wxb[2 * j],     ab0);
            aa1 = ffma2(p1, wxa[2 * j + 1], aa1);
            ab1 = ffma2(p1, wxb[2 * j + 1], ab1);
            if (j + 4 < 16) {                  // refill ring slot s with chunk j+4
                ulonglong2 v = sx4[w][j + 4];
                xp[2 * s] = v.x; xp[2 * s + 1] = v.y;
            }
        }
#pragma unroll
        for (int k = 0; k < 8; k++) {
            if (k & 1) { aa1 = ffma2(hp[k], wha[k], aa1); ab1 = ffma2(hp[k], whb[k], ab1); }
            else       { aa0 = ffma2(hp[k], wha[k], aa0); ab0 = ffma2(hp[k], whb[k], ab0); }
        }

        ULL sa = fadd2(aa0, aa1), sb = fadd2(ab0, ab1);
        float a0, a1, b0, b1;
        f2unpack(sa, a0, a1);
        f2unpack(sb, b0, b1);
        float za = a0 + a1;   // lane<16: i preact | lane>=16: f preact
        float zb = b0 + b1;   // lane<16: g preact | lane>=16: o preact

        float v1 = fast_sigmoid(za);                                  // i or f
        float v2 = (lane < 16) ? fmaxf(zb, 0.0f) : fast_sigmoid(zb);  // g or o

        float fpart = __shfl_xor_sync(0xFFFFFFFFu, v1, 16);  // lanes<16 get f
        float opart = __shfl_xor_sync(0xFFFFFFFFu, v2, 16);  // lanes<16 get o

        c_state = fpart * c_state + v1 * v2;                 // valid lanes 0..15
        float hnew = opart * fmaxf(c_state, 0.0f);
        if (lane < 16) ((float*)sh4[w])[lane] = hnew;
        // next-iteration __syncwarp() orders this store before the h reload.

        xc = xn;
        xn = xf;
    }
    __syncwarp();

    // ---- MLP head: lane 0 per warp ----
    if (lane == 0) {
        const float* hT = (const float*)sh4[w];
        float x2v[8];
#pragma unroll
        for (int u = 0; u < 8; u++) {
            float s = __ldg(&b2[u]);
#pragma unroll
            for (int j = 0; j < 16; j++) s += hT[j] * __ldg(&W2[j * 8 + u]);
            x2v[u] = fmaxf(s, 0.0f);
        }
        float x3v[4];
#pragma unroll
        for (int u = 0; u < 4; u++) {
            float s = __ldg(&b3[u]);
#pragma unroll
            for (int j = 0; j < 8; j++) s += x2v[j] * __ldg(&W3[j * 4 + u]);
            x3v[u] = fmaxf(s, 0.0f);
        }
        float s = __ldg(&bo[0]);
#pragma unroll
        for (int u = 0; u < 4; u++) s += x3v[u] * __ldg(&Wo[u]);
        out[batch] = fast_sigmoid(s);
    }
}

extern "C" void kernel_launch(void* const* d_in, const int* in_sizes, int n_in,
                              void* d_out, int out_size) {
    const float* x  = (const float*)d_in[0];
    const float* Wx = (const float*)d_in[1];
    const float* Wh = (const float*)d_in[2];
    const float* b  = (const float*)d_in[3];
    const float* W2 = (const float*)d_in[4];
    const float* b2 = (const float*)d_in[5];
    const float* W3 = (const float*)d_in[6];
    const float* b3 = (const float*)d_in[7];
    const float* Wo = (const float*)d_in[8];
    const float* bo = (const float*)d_in[9];
    float* out = (float*)d_out;

    lstm_fused_kernel<<<Bsz / 4, 128>>>(x, Wx, Wh, b, W2, b2, W3, b3, Wo, bo, out);
}

// round 5
// speedup vs baseline: 1.9089x; 1.9089x over previous
#include <cuda_runtime.h>
#include <cuda_bf16.h>
#include <cstdint>

#define ULL unsigned long long

static constexpr int Bsz = 2048;
static constexpr int T   = 512;
static constexpr int G   = 64;   // 4*H gate columns

// scratch: xz = x*Wx (no bias), row-major [B*T][64]  (268 MB)
__device__ float g_xz[(size_t)Bsz * T * G];

// ---------------- helpers ----------------
__device__ __forceinline__ ULL f2pack(float lo, float hi) {
    ULL r; asm("mov.b64 %0, {%1, %2};" : "=l"(r) : "f"(lo), "f"(hi)); return r;
}
__device__ __forceinline__ void f2unpack(ULL v, float& lo, float& hi) {
    asm("mov.b64 {%0, %1}, %2;" : "=f"(lo), "=f"(hi) : "l"(v));
}
__device__ __forceinline__ ULL ffma2(ULL a, ULL b, ULL c) {
    ULL d; asm("fma.rn.f32x2 %0, %1, %2, %3;" : "=l"(d) : "l"(a), "l"(b), "l"(c)); return d;
}
__device__ __forceinline__ ULL fadd2(ULL a, ULL b) {
    ULL d; asm("add.rn.f32x2 %0, %1, %2;" : "=l"(d) : "l"(a), "l"(b)); return d;
}
__device__ __forceinline__ float fast_sigmoid(float x) {
    return __fdividef(1.0f, 1.0f + __expf(-x));
}

// pack two f32 into bf16x2 (x0 -> low half, x1 -> high half)
__device__ __forceinline__ uint32_t bf16x2_hi(float x0, float x1) {
    uint32_t r; asm("cvt.rn.bf16x2.f32 %0, %1, %2;" : "=r"(r) : "f"(x1), "f"(x0)); return r;
}
// residual (x - bf16(x)) packed as bf16x2, given the hi packing
__device__ __forceinline__ uint32_t bf16x2_lo(float x0, float x1, uint32_t hi) {
    float h0 = __uint_as_float(hi << 16);
    float h1 = __uint_as_float(hi & 0xFFFF0000u);
    return bf16x2_hi(x0 - h0, x1 - h1);
}

// m16n8k16 row.col bf16 MMA, f32 accumulate in place
__device__ __forceinline__ void mma16816(float* c, const uint32_t* a, const uint32_t* b) {
    asm("mma.sync.aligned.m16n8k16.row.col.f32.bf16.bf16.f32 "
        "{%0,%1,%2,%3}, {%4,%5,%6,%7}, {%8,%9}, {%0,%1,%2,%3};"
        : "+f"(c[0]), "+f"(c[1]), "+f"(c[2]), "+f"(c[3])
        : "r"(a[0]), "r"(a[1]), "r"(a[2]), "r"(a[3]), "r"(b[0]), "r"(b[1]));
}

// ============================================================================
// Kernel 1: xz = x * Wx   via HMMA m16n8k16, bf16 hi/lo split (3 products).
// A = x rows (M), B = Wx (K=64 x N=64) held as register fragments.
// Each warp: 8 groups of 16 rows = 128 rows. Block = 4 warps = 512 rows.
// ============================================================================
__global__ void __launch_bounds__(128)
gemm_xz_kernel(const float* __restrict__ x, const float* __restrict__ Wx)
{
    const int lane = threadIdx.x & 31;
    const int w    = threadIdx.x >> 5;
    const int r    = lane >> 2;        // 0..7
    const int cq   = (lane & 3) * 2;   // 0,2,4,6

    const size_t mbase = (size_t)blockIdx.x * 512 + (size_t)w * 128;

    // ---- B fragments: Wx as col-major K x N frags, hi & lo ----
    // b0 holds {Wx[k0][n], Wx[k0+1][n]}, b1 holds {Wx[k0+8][n], Wx[k0+9][n]}
    uint32_t bh[8][4][2], bl[8][4][2];
#pragma unroll
    for (int nt = 0; nt < 8; nt++) {
        const int n = nt * 8 + r;
#pragma unroll
        for (int ks = 0; ks < 4; ks++) {
            const int k0 = ks * 16 + cq;
            float w00 = __ldg(&Wx[(k0)     * 64 + n]);
            float w01 = __ldg(&Wx[(k0 + 1) * 64 + n]);
            float w10 = __ldg(&Wx[(k0 + 8) * 64 + n]);
            float w11 = __ldg(&Wx[(k0 + 9) * 64 + n]);
            bh[nt][ks][0] = bf16x2_hi(w00, w01);
            bh[nt][ks][1] = bf16x2_hi(w10, w11);
            bl[nt][ks][0] = bf16x2_lo(w00, w01, bh[nt][ks][0]);
            bl[nt][ks][1] = bf16x2_lo(w10, w11, bh[nt][ks][1]);
        }
    }

#pragma unroll 1
    for (int g = 0; g < 8; g++) {
        const float* xrow = x + (mbase + (size_t)g * 16) * 64;

        // ---- A raw loads: 16 x LDG.64, all independent (MLP=16) ----
        float2 ar[4][4];
#pragma unroll
        for (int ks = 0; ks < 4; ks++) {
            const int k0 = ks * 16 + cq;
            ar[ks][0] = *reinterpret_cast<const float2*>(xrow + (r)     * 64 + k0);
            ar[ks][1] = *reinterpret_cast<const float2*>(xrow + (r + 8) * 64 + k0);
            ar[ks][2] = *reinterpret_cast<const float2*>(xrow + (r)     * 64 + k0 + 8);
            ar[ks][3] = *reinterpret_cast<const float2*>(xrow + (r + 8) * 64 + k0 + 8);
        }

        float c[8][4];
#pragma unroll
        for (int nt = 0; nt < 8; nt++)
#pragma unroll
            for (int e = 0; e < 4; e++) c[nt][e] = 0.0f;

#pragma unroll
        for (int ks = 0; ks < 4; ks++) {
            uint32_t ah[4], al[4];
#pragma unroll
            for (int j = 0; j < 4; j++) {
                ah[j] = bf16x2_hi(ar[ks][j].x, ar[ks][j].y);
                al[j] = bf16x2_lo(ar[ks][j].x, ar[ks][j].y, ah[j]);
            }
#pragma unroll
            for (int nt = 0; nt < 8; nt++) {
                mma16816(c[nt], ah, bh[nt][ks]);   // hi*hi
                mma16816(c[nt], ah, bl[nt][ks]);   // hi*lo
                mma16816(c[nt], al, bh[nt][ks]);   // lo*hi
            }
        }

        // ---- store: c0,c1 -> (row, cols 8nt+cq..+1); c2,c3 -> row+8 ----
        float* orow = g_xz + (mbase + (size_t)g * 16) * 64;
#pragma unroll
        for (int nt = 0; nt < 8; nt++) {
            *reinterpret_cast<float2*>(orow + (r)     * 64 + nt * 8 + cq) =
                make_float2(c[nt][0], c[nt][1]);
            *reinterpret_cast<float2*>(orow + (r + 8) * 64 + nt * 8 + cq) =
                make_float2(c[nt][2], c[nt][3]);
        }
    }
}

// ============================================================================
// Kernel 2: recurrence. One warp per batch; lane l owns gate cols l and l+32.
// z_t = xz_t + bias + h*Wh ; Keras LSTM with relu cell activation; MLP head.
// ============================================================================
__global__ void __launch_bounds__(128)
lstm_rec_kernel(const float* __restrict__ Wh,   // [16, 64]
                const float* __restrict__ bias, // [64]
                const float* __restrict__ W2, const float* __restrict__ b2,
                const float* __restrict__ W3, const float* __restrict__ b3,
                const float* __restrict__ Wo, const float* __restrict__ bo,
                float* __restrict__ out)
{
    const int lane  = threadIdx.x & 31;
    const int w     = threadIdx.x >> 5;
    const int batch = blockIdx.x * 4 + w;

    __shared__ __align__(16) ULL sh2[4][8];   // h as 8 packed pairs per warp

    ULL wha[8], whb[8];
#pragma unroll
    for (int kk = 0; kk < 8; kk++) {
        wha[kk] = f2pack(__ldg(&Wh[(2 * kk) * G + lane]),
                         __ldg(&Wh[(2 * kk + 1) * G + lane]));
        whb[kk] = f2pack(__ldg(&Wh[(2 * kk) * G + lane + 32]),
                         __ldg(&Wh[(2 * kk + 1) * G + lane + 32]));
    }
    const float bA = __ldg(&bias[lane]);
    const float bB = __ldg(&bias[lane + 32]);

    if (lane < 16) ((float*)sh2[w])[lane] = 0.0f;
    float c_state = 0.0f;

    // z stream: lane reads cols lane and lane+32 (both warp-coalesced), 8-deep prefetch
    const float* z0 = g_xz + (size_t)batch * T * 64 + lane;
    float zb0[8], zb1[8];
#pragma unroll
    for (int i = 0; i < 8; i++) {
        zb0[i] = __ldg(z0 + (size_t)i * 64);
        zb1[i] = __ldg(z0 + (size_t)i * 64 + 32);
    }
    __syncwarp();

    for (int tb = 0; tb < T; tb += 8) {
#pragma unroll
        for (int u = 0; u < 8; u++) {
            const int t = tb + u;
            float zxa = zb0[u] + bA;
            float zxb = zb1[u] + bB;
            if (t + 8 < T) {
                zb0[u] = __ldg(z0 + (size_t)(t + 8) * 64);
                zb1[u] = __ldg(z0 + (size_t)(t + 8) * 64 + 32);
            }

            // h pairs (broadcast LDS.128 x4); previous-step store ordered by
            // the __syncwarp at the end of the previous iteration.
            ULL hp[8];
            {
                ulonglong2 v0 = reinterpret_cast<ulonglong2*>(sh2[w])[0];
                ulonglong2 v1 = reinterpret_cast<ulonglong2*>(sh2[w])[1];
                ulonglong2 v2 = reinterpret_cast<ulonglong2*>(sh2[w])[2];
                ulonglong2 v3 = reinterpret_cast<ulonglong2*>(sh2[w])[3];
                hp[0] = v0.x; hp[1] = v0.y; hp[2] = v1.x; hp[3] = v1.y;
                hp[4] = v2.x; hp[5] = v2.y; hp[6] = v3.x; hp[7] = v3.y;
            }

            ULL aa0 = f2pack(zxa, 0.0f), aa1 = 0ULL;
            ULL ab0 = f2pack(zxb, 0.0f), ab1 = 0ULL;
#pragma unroll
            for (int k = 0; k < 8; k++) {
                if (k & 1) { aa1 = ffma2(hp[k], wha[k], aa1); ab1 = ffma2(hp[k], whb[k], ab1); }
                else       { aa0 = ffma2(hp[k], wha[k], aa0); ab0 = ffma2(hp[k], whb[k], ab0); }
            }
            ULL sa = fadd2(aa0, aa1), sb = fadd2(ab0, ab1);
            float a0, a1, b0, b1;
            f2unpack(sa, a0, a1);
            f2unpack(sb, b0, b1);
            float za = a0 + a1;   // lane<16: i preact | lane>=16: f preact
            float zbv = b0 + b1;  // lane<16: g preact | lane>=16: o preact

            float v1 = fast_sigmoid(za);                                    // i or f
            float v2 = (lane < 16) ? fmaxf(zbv, 0.0f) : fast_sigmoid(zbv);  // g or o

            float fpart = __shfl_xor_sync(0xFFFFFFFFu, v1, 16);  // lanes<16 get f
            float opart = __shfl_xor_sync(0xFFFFFFFFu, v2, 16);  // lanes<16 get o

            c_state = fpart * c_state + v1 * v2;                 // valid lanes 0..15
            float hnew = opart * fmaxf(c_state, 0.0f);
            if (lane < 16) ((float*)sh2[w])[lane] = hnew;
            __syncwarp();
        }
    }

    // ---- MLP head: lane 0 per warp ----
    if (lane == 0) {
        const float* hT = (const float*)sh2[w];
        float x2v[8];
#pragma unroll
        for (int u = 0; u < 8; u++) {
            float s = __ldg(&b2[u]);
#pragma unroll
            for (int j = 0; j < 16; j++) s += hT[j] * __ldg(&W2[j * 8 + u]);
            x2v[u] = fmaxf(s, 0.0f);
        }
        float x3v[4];
#pragma unroll
        for (int u = 0; u < 4; u++) {
            float s = __ldg(&b3[u]);
#pragma unroll
            for (int j = 0; j < 8; j++) s += x2v[j] * __ldg(&W3[j * 4 + u]);
            x3v[u] = fmaxf(s, 0.0f);
        }
        float s = __ldg(&bo[0]);
#pragma unroll
        for (int u = 0; u < 4; u++) s += x3v[u] * __ldg(&Wo[u]);
        out[batch] = fast_sigmoid(s);
    }
}

extern "C" void kernel_launch(void* const* d_in, const int* in_sizes, int n_in,
                              void* d_out, int out_size) {
    const float* x  = (const float*)d_in[0];
    const float* Wx = (const float*)d_in[1];
    const float* Wh = (const float*)d_in[2];
    const float* b  = (const float*)d_in[3];
    const float* W2 = (const float*)d_in[4];
    const float* b2 = (const float*)d_in[5];
    const float* W3 = (const float*)d_in[6];
    const float* b3 = (const float*)d_in[7];
    const float* Wo = (const float*)d_in[8];
    const float* bo = (const float*)d_in[9];
    float* out = (float*)d_out;

    // Pass 1: xz = x*Wx on HMMA tensor cores (bf16 hi/lo split, 3 products)
    gemm_xz_kernel<<<(Bsz * T) / 512, 128>>>(x, Wx);
    // Pass 2: recurrence + MLP head (stream-ordered after pass 1)
    lstm_rec_kernel<<<Bsz / 4, 128>>>(Wh, b, W2, b2, W3, b3, Wo, bo, out);
}

// round 10
// speedup vs baseline: 2.1991x; 1.1520x over previous
#include <cuda_runtime.h>
#include <cuda_bf16.h>
#include <cstdint>

#define ULL unsigned long long

static constexpr int Bsz = 2048;
static constexpr int T   = 512;
static constexpr int CH  = 16;        // timesteps per chunk
static constexpr int NCH = T / CH;    // 32 chunks
static constexpr int ZP  = 68;        // zbuf pitch (floats), pads bank pattern

// ---------------- helpers ----------------
__device__ __forceinline__ ULL f2pack(float lo, float hi) {
    ULL r; asm("mov.b64 %0, {%1, %2};" : "=l"(r) : "f"(lo), "f"(hi)); return r;
}
__device__ __forceinline__ void f2unpack(ULL v, float& lo, float& hi) {
    asm("mov.b64 {%0, %1}, %2;" : "=f"(lo), "=f"(hi) : "l"(v));
}
__device__ __forceinline__ ULL ffma2(ULL a, ULL b, ULL c) {
    ULL d; asm("fma.rn.f32x2 %0, %1, %2, %3;" : "=l"(d) : "l"(a), "l"(b), "l"(c)); return d;
}
__device__ __forceinline__ ULL fadd2(ULL a, ULL b) {
    ULL d; asm("add.rn.f32x2 %0, %1, %2;" : "=l"(d) : "l"(a), "l"(b)); return d;
}
__device__ __forceinline__ float fast_sigmoid(float x) {
    // 1/(1+2^(-x*log2e)) : FMUL + MUFU.EX2 + FADD + MUFU.RCP
    float e, r;
    asm("ex2.approx.f32 %0, %1;" : "=f"(e) : "f"(x * -1.4426950408889634f));
    asm("rcp.approx.f32 %0, %1;" : "=f"(r) : "f"(1.0f + e));
    return r;
}
__device__ __forceinline__ uint32_t bf16x2_hi(float x0, float x1) {
    uint32_t r; asm("cvt.rn.bf16x2.f32 %0, %1, %2;" : "=r"(r) : "f"(x1), "f"(x0)); return r;
}
__device__ __forceinline__ uint32_t bf16x2_lo(float x0, float x1, uint32_t hi) {
    float h0 = __uint_as_float(hi << 16);
    float h1 = __uint_as_float(hi & 0xFFFF0000u);
    return bf16x2_hi(x0 - h0, x1 - h1);
}
__device__ __forceinline__ void mma16816(float* c, const uint32_t* a, const uint32_t* b) {
    asm("mma.sync.aligned.m16n8k16.row.col.f32.bf16.bf16.f32 "
        "{%0,%1,%2,%3}, {%4,%5,%6,%7}, {%8,%9}, {%0,%1,%2,%3};"
        : "+f"(c[0]), "+f"(c[1]), "+f"(c[2]), "+f"(c[3])
        : "r"(a[0]), "r"(a[1]), "r"(a[2]), "r"(a[3]), "r"(b[0]), "r"(b[1]));
}

// ============================================================================
// Fused LSTM: each warp owns one batch. Per 16-step chunk the warp first
// produces z = x*Wx + b for those steps via HMMA into its private smem buffer
// (x loads issued one chunk ahead), then runs the 16 recurrence steps.
// ============================================================================
__global__ void __launch_bounds__(128, 4)
lstm_fused(const float* __restrict__ x,
           const float* __restrict__ Wx,   // [64, 64]
           const float* __restrict__ Wh,   // [16, 64]
           const float* __restrict__ bias, // [64]
           const float* __restrict__ W2, const float* __restrict__ b2,
           const float* __restrict__ W3, const float* __restrict__ b3,
           const float* __restrict__ Wo, const float* __restrict__ bo,
           float* __restrict__ out)
{
    const int lane = threadIdx.x & 31;
    const int w    = threadIdx.x >> 5;
    const int batch = blockIdx.x * 4 + w;
    const int r  = lane >> 2;          // 0..7
    const int cq = (lane & 3) * 2;     // 0,2,4,6

    __shared__ float zbuf[4][CH][ZP];                   // per-warp z chunk
    __shared__ uint2 sBh[4][8][32], sBl[4][8][32];      // Wx frags hi/lo
    __shared__ float2 sbias[8][4];                      // bias frags
    __shared__ __align__(16) float sh[4][32];           // h state (16 used)

    // ---- build Wx fragments: warp w covers k-step ks=w ----
    {
        const int k0 = w * 16 + cq;
#pragma unroll
        for (int nt = 0; nt < 8; nt++) {
            const int n = nt * 8 + r;
            float w00 = __ldg(&Wx[(k0)     * 64 + n]);
            float w01 = __ldg(&Wx[(k0 + 1) * 64 + n]);
            float w10 = __ldg(&Wx[(k0 + 8) * 64 + n]);
            float w11 = __ldg(&Wx[(k0 + 9) * 64 + n]);
            uint32_t h0 = bf16x2_hi(w00, w01);
            uint32_t h1 = bf16x2_hi(w10, w11);
            sBh[w][nt][lane] = make_uint2(h0, h1);
            sBl[w][nt][lane] = make_uint2(bf16x2_lo(w00, w01, h0),
                                          bf16x2_lo(w10, w11, h1));
        }
    }
    if (threadIdx.x < 32) {
        int nt = threadIdx.x >> 2, q = threadIdx.x & 3;
        sbias[nt][q] = make_float2(__ldg(&bias[nt * 8 + 2 * q]),
                                   __ldg(&bias[nt * 8 + 2 * q + 1]));
    }

    // ---- Wh weight pairs in registers (cols lane, lane+32) ----
    ULL wha[8], whb[8];
#pragma unroll
    for (int kk = 0; kk < 8; kk++) {
        wha[kk] = f2pack(__ldg(&Wh[(2 * kk) * 64 + lane]),
                         __ldg(&Wh[(2 * kk + 1) * 64 + lane]));
        whb[kk] = f2pack(__ldg(&Wh[(2 * kk) * 64 + lane + 32]),
                         __ldg(&Wh[(2 * kk + 1) * 64 + lane + 32]));
    }

    sh[w][lane] = 0.0f;
    float c_state = 0.0f;
    __syncthreads();

    const float* xb = x + (size_t)batch * T * 64;
    float2 ar[4][4];   // raw x for the next chunk to produce

    // load x rows (t0+r, t0+r+8) per k-slice — A-frag layout of m16n8k16
    auto load_x = [&](int t0) {
#pragma unroll
        for (int ks = 0; ks < 4; ks++) {
            const int k0 = ks * 16 + cq;
            ar[ks][0] = *(const float2*)(xb + (size_t)(t0 + r)     * 64 + k0);
            ar[ks][1] = *(const float2*)(xb + (size_t)(t0 + r + 8) * 64 + k0);
            ar[ks][2] = *(const float2*)(xb + (size_t)(t0 + r)     * 64 + k0 + 8);
            ar[ks][3] = *(const float2*)(xb + (size_t)(t0 + r + 8) * 64 + k0 + 8);
        }
    };

    // produce z chunk from ar into zbuf[w] (bias folded)
    auto produce = [&]() {
        uint32_t ah[4][4], al[4][4];
#pragma unroll
        for (int ks = 0; ks < 4; ks++)
#pragma unroll
            for (int j = 0; j < 4; j++) {
                ah[ks][j] = bf16x2_hi(ar[ks][j].x, ar[ks][j].y);
                al[ks][j] = bf16x2_lo(ar[ks][j].x, ar[ks][j].y, ah[ks][j]);
            }
#pragma unroll
        for (int np = 0; np < 4; np++) {
            float c0[4] = {0, 0, 0, 0}, c1[4] = {0, 0, 0, 0};
#pragma unroll
            for (int ks = 0; ks < 4; ks++) {
                uint2 bh0 = sBh[ks][2 * np][lane],     bl0 = sBl[ks][2 * np][lane];
                uint2 bh1 = sBh[ks][2 * np + 1][lane], bl1 = sBl[ks][2 * np + 1][lane];
                mma16816(c0, ah[ks], &bh0.x);
                mma16816(c0, ah[ks], &bl0.x);
                mma16816(c0, al[ks], &bh0.x);
                mma16816(c1, ah[ks], &bh1.x);
                mma16816(c1, ah[ks], &bl1.x);
                mma16816(c1, al[ks], &bh1.x);
            }
            float2 bA0 = sbias[2 * np][cq >> 1];
            float2 bA1 = sbias[2 * np + 1][cq >> 1];
            *(float2*)&zbuf[w][r][2 * np * 8 + cq] =
                make_float2(c0[0] + bA0.x, c0[1] + bA0.y);
            *(float2*)&zbuf[w][r + 8][2 * np * 8 + cq] =
                make_float2(c0[2] + bA0.x, c0[3] + bA0.y);
            *(float2*)&zbuf[w][r][(2 * np + 1) * 8 + cq] =
                make_float2(c1[0] + bA1.x, c1[1] + bA1.y);
            *(float2*)&zbuf[w][r + 8][(2 * np + 1) * 8 + cq] =
                make_float2(c1[2] + bA1.x, c1[3] + bA1.y);
        }
    };

    load_x(0);
    produce();          // chunk 0 ready in zbuf
    load_x(CH);         // raw x for chunk 1

#pragma unroll 1
    for (int ch = 0; ch < NCH; ch++) {
        __syncwarp();   // z STS (and previous h store) visible to all lanes

        float zA = zbuf[w][0][lane];
        float zB = zbuf[w][0][lane + 32];

#pragma unroll
        for (int tl = 0; tl < CH; tl++) {
            // h pairs: 4x LDS.128 broadcast (ordered by syncwarp)
            ULL hp[8];
            {
                ulonglong2 v0 = ((ulonglong2*)sh[w])[0];
                ulonglong2 v1 = ((ulonglong2*)sh[w])[1];
                ulonglong2 v2 = ((ulonglong2*)sh[w])[2];
                ulonglong2 v3 = ((ulonglong2*)sh[w])[3];
                hp[0] = v0.x; hp[1] = v0.y; hp[2] = v1.x; hp[3] = v1.y;
                hp[4] = v2.x; hp[5] = v2.y; hp[6] = v3.x; hp[7] = v3.y;
            }
            float zAn = 0.0f, zBn = 0.0f;
            if (tl + 1 < CH) {                 // compile-time guard (unrolled)
                zAn = zbuf[w][tl + 1][lane];
                zBn = zbuf[w][tl + 1][lane + 32];
            }

            ULL aa0 = f2pack(zA, 0.0f), aa1 = 0ULL;
            ULL ab0 = f2pack(zB, 0.0f), ab1 = 0ULL;
#pragma unroll
            for (int k = 0; k < 8; k++) {
                if (k & 1) { aa1 = ffma2(hp[k], wha[k], aa1); ab1 = ffma2(hp[k], whb[k], ab1); }
                else       { aa0 = ffma2(hp[k], wha[k], aa0); ab0 = ffma2(hp[k], whb[k], ab0); }
            }
            ULL sa = fadd2(aa0, aa1), sb = fadd2(ab0, ab1);
            float a0, a1, b0, b1;
            f2unpack(sa, a0, a1);
            f2unpack(sb, b0, b1);
            float za  = a0 + a1;   // lane<16: i | lane>=16: f
            float zbv = b0 + b1;   // lane<16: g | lane>=16: o

            float v1 = fast_sigmoid(za);
            float v2 = (lane < 16) ? fmaxf(zbv, 0.0f) : fast_sigmoid(zbv);

            float fpart = __shfl_xor_sync(0xFFFFFFFFu, v1, 16);
            float opart = __shfl_xor_sync(0xFFFFFFFFu, v2, 16);

            c_state = fpart * c_state + v1 * v2;          // valid lanes 0..15
            float hnew = opart * fmaxf(c_state, 0.0f);
            sh[w][lane] = hnew;                           // branchless (32-wide)
            __syncwarp();

            zA = zAn; zB = zBn;
        }

        // produce next chunk (consume of this chunk already fenced by syncwarp)
        if (ch + 1 < NCH) {
            produce();
            if (ch + 2 < NCH) load_x((ch + 2) * CH);
        }
    }

    // ---- MLP head: lane 0 per warp ----
    if (lane == 0) {
        const float* hT = sh[w];
        float x2v[8];
#pragma unroll
        for (int u = 0; u < 8; u++) {
            float s = __ldg(&b2[u]);
#pragma unroll
            for (int j = 0; j < 16; j++) s += hT[j] * __ldg(&W2[j * 8 + u]);
            x2v[u] = fmaxf(s, 0.0f);
        }
        float x3v[4];
#pragma unroll
        for (int u = 0; u < 4; u++) {
            float s = __ldg(&b3[u]);
#pragma unroll
            for (int j = 0; j < 8; j++) s += x2v[j] * __ldg(&W3[j * 4 + u]);
            x3v[u] = fmaxf(s, 0.0f);
        }
        float s = __ldg(&bo[0]);
#pragma unroll
        for (int u = 0; u < 4; u++) s += x3v[u] * __ldg(&Wo[u]);
        out[batch] = fast_sigmoid(s);
    }
}

extern "C" void kernel_launch(void* const* d_in, const int* in_sizes, int n_in,
                              void* d_out, int out_size) {
    (void)in_sizes; (void)n_in; (void)out_size;
    const float* x  = (const float*)d_in[0];
    const float* Wx = (const float*)d_in[1];
    const float* Wh = (const float*)d_in[2];
    const float* b  = (const float*)d_in[3];
    const float* W2 = (const float*)d_in[4];
    const float* b2 = (const float*)d_in[5];
    const float* W3 = (const float*)d_in[6];
    const float* b3 = (const float*)d_in[7];
    const float* Wo = (const float*)d_in[8];
    const float* bo = (const float*)d_in[9];
    float* out = (float*)d_out;

    lstm_fused<<<Bsz / 4, 128>>>(x, Wx, Wh, b, W2, b2, W3, b3, Wo, bo, out);
}